// round 13
// baseline (speedup 1.0000x reference)
#include <cuda_runtime.h>
#include <math_constants.h>

// VerticalLinePool: out[..., h, :] = max_{h' >= h} x[..., h', :]
// x shape (8, 128, 256, 256) fp32, NCHW. Reverse suffix-max (running max
// scanning bottom-to-top) along H.
//
// One thread per (n, c, w4) float4 column; serial scan h = 255 -> 0,
// initialized with -INF so the loop is a clean 256 = 16x16 unroll with no
// peel/remainder. 65,536 threads = 512 blocks x 128. Coalesced 512B/warp
// per h-row, streaming ld/st hints (zero reuse; don't pollute L2).

#define H_DIM 256
#define W4_DIM 64              // W/4 = 256/4 float4 lanes per row

__global__ __launch_bounds__(128) void vlinepool_kernel(
    const float4* __restrict__ x, float4* __restrict__ out)
{
    int t = blockIdx.x * blockDim.x + threadIdx.x;   // 0 .. 65535, exact grid

    int plane = t >> 6;        // (n*C + c) index, 0..1023
    int w4    = t & 63;        // float4 lane within row

    // Base of this column at h = 0; scan runs from the h = H-1 end downward.
    int base = plane * (H_DIM * W4_DIM) + w4;
    const float4* xp = x   + base;
    float4*       op = out + base;

    float4 m = make_float4(-CUDART_INF_F, -CUDART_INF_F,
                           -CUDART_INF_F, -CUDART_INF_F);

    #pragma unroll 16
    for (int h = H_DIM - 1; h >= 0; --h) {
        int off = h * W4_DIM;
        float4 v = __ldcs(xp + off);
        m.x = fmaxf(m.x, v.x);
        m.y = fmaxf(m.y, v.y);
        m.z = fmaxf(m.z, v.z);
        m.w = fmaxf(m.w, v.w);
        __stcs(op + off, m);
    }
}

extern "C" void kernel_launch(void* const* d_in, const int* in_sizes, int n_in,
                              void* d_out, int out_size)
{
    const float4* x   = (const float4*)d_in[0];
    float4*       out = (float4*)d_out;

    // 1024 (n,c) planes * 64 float4 lanes = 65,536 columns, one thread each.
    vlinepool_kernel<<<512, 128>>>(x, out);
}

// round 17
// speedup vs baseline: 1.7366x; 1.7366x over previous
#include <cuda_runtime.h>
#include <math_constants.h>

// VerticalLinePool: out[..., h, :] = max_{h' >= h} x[..., h', :]
// x shape (8, 128, 256, 256) fp32 NCHW. Reverse suffix-max along H.
//
// One thread per (n,c,w4) float4 column, scanning h = 255 -> 0.
// R13 ncu: dram 38%, regs=26 -> ptxas serialized load/max/store (MLP~2).
// Fix: explicit double-buffered batches of 8 float4 so ~8-16 loads are
// outstanding per thread while the previous batch is reduced and stored.

#define H_DIM   256
#define W4_DIM  64              // W/4 float4 lanes per row
#define BATCH   8
#define NGROUPS (H_DIM / BATCH) // 32

// Load group g (h = 255-8g .. 248-8g) into buf[0..7].
#define LOAD_GROUP(buf, g)                                              \
    {                                                                   \
        const float4* pg = px + (H_DIM - 1 - (g) * BATCH) * W4_DIM;     \
        _Pragma("unroll")                                               \
        for (int i = 0; i < BATCH; i++)                                 \
            buf[i] = __ldcs(pg - i * W4_DIM);                           \
    }

// Fold group g into running max m and store results.
#define COMP_GROUP(buf, g)                                              \
    {                                                                   \
        float4* qg = po + (H_DIM - 1 - (g) * BATCH) * W4_DIM;           \
        _Pragma("unroll")                                               \
        for (int i = 0; i < BATCH; i++) {                               \
            m.x = fmaxf(m.x, buf[i].x);                                 \
            m.y = fmaxf(m.y, buf[i].y);                                 \
            m.z = fmaxf(m.z, buf[i].z);                                 \
            m.w = fmaxf(m.w, buf[i].w);                                 \
            __stcs(qg - i * W4_DIM, m);                                 \
        }                                                               \
    }

__global__ __launch_bounds__(128) void vlinepool_kernel(
    const float4* __restrict__ x, float4* __restrict__ out)
{
    int t = blockIdx.x * blockDim.x + threadIdx.x;   // 0..65535, exact grid

    int plane = t >> 6;        // (n*C + c), 0..1023
    int w4    = t & 63;        // float4 lane within row

    int base = plane * (H_DIM * W4_DIM) + w4;
    const float4* px = x   + base;
    float4*       po = out + base;

    float4 m = make_float4(-CUDART_INF_F, -CUDART_INF_F,
                           -CUDART_INF_F, -CUDART_INF_F);

    float4 A[BATCH], B[BATCH];

    // Software pipeline: loads for the next group are in flight while the
    // current group is reduced + stored.
    LOAD_GROUP(A, 0);
    #pragma unroll 1
    for (int p = 0; p < (NGROUPS / 2) - 1; p++) {   // p = 0..14
        int g = 2 * p;
        LOAD_GROUP(B, g + 1);
        COMP_GROUP(A, g);
        LOAD_GROUP(A, g + 2);
        COMP_GROUP(B, g + 1);
    }
    LOAD_GROUP(B, NGROUPS - 1);
    COMP_GROUP(A, NGROUPS - 2);
    COMP_GROUP(B, NGROUPS - 1);
}

extern "C" void kernel_launch(void* const* d_in, const int* in_sizes, int n_in,
                              void* d_out, int out_size)
{
    const float4* x   = (const float4*)d_in[0];
    float4*       out = (float4*)d_out;

    // 1024 (n,c) planes * 64 float4 lanes = 65,536 columns, one thread each.
    vlinepool_kernel<<<512, 128>>>(x, out);
}